// round 1
// baseline (speedup 1.0000x reference)
#include <cuda_runtime.h>
#include <cuda_bf16.h>
#include <math.h>

// Problem constants
#define BATCH   8
#define DIM     1024      // embedding dim C
#define HW      1024      // 32*32 spatial
#define NROW    8192      // BATCH*HW flattened positions
#define NCODE   8192      // codebook size
#define ZQ_ELEMS (BATCH*DIM*HW)       // 8,388,608
#define OFF_LOSS  ZQ_ELEMS
#define OFF_PERP  (ZQ_ELEMS + 1)
#define OFF_IDX   (ZQ_ELEMS + 2)

// ---------------- device scratch (no dynamic allocation allowed) -------------
__device__ float  g_zflat[(size_t)NROW * DIM];   // 32 MB: z in [n][d] layout
__device__ float  g_S[NROW];                     // |z_n|^2
__device__ float  g_T[NCODE];                    // |e_k|^2
__device__ float  g_pval[(size_t)NROW * 64];     // per-(row, codeTile) min value
__device__ int    g_pidx[(size_t)NROW * 64];     // per-(row, codeTile) argmin
__device__ int    g_idx[NROW];
__device__ int    g_hist[NCODE];
__device__ double g_loss;

// ---------------- kernel 0: zero accumulators --------------------------------
__global__ void vq_zero_kernel() {
    int t = blockIdx.x * blockDim.x + threadIdx.x;
    if (t < NCODE) g_hist[t] = 0;
    if (t == 0) g_loss = 0.0;
}

// ---------------- kernel 1: transpose z[b][c][hw] -> zflat[b*HW+hw][c] -------
__global__ void vq_transpose_kernel(const float* __restrict__ z) {
    __shared__ float tile[32][33];
    int b = blockIdx.z;
    int hw0 = blockIdx.x * 32;
    int c0  = blockIdx.y * 32;
    const float* src = z + ((size_t)b << 20);          // b * 1024*1024
    float* dst = g_zflat + ((size_t)b << 20);
    #pragma unroll
    for (int r = threadIdx.y; r < 32; r += 8)
        tile[r][threadIdx.x] = src[(size_t)(c0 + r) * HW + hw0 + threadIdx.x];
    __syncthreads();
    #pragma unroll
    for (int r = threadIdx.y; r < 32; r += 8)
        dst[(size_t)(hw0 + r) * DIM + c0 + threadIdx.x] = tile[threadIdx.x][r];
}

// ---------------- kernel 2: row squared-norms for zflat and emb --------------
__global__ void vq_rowsum_kernel(const float* __restrict__ emb) {
    int gw   = (blockIdx.x * blockDim.x + threadIdx.x) >> 5;  // global warp id
    int lane = threadIdx.x & 31;
    if (gw >= NROW + NCODE) return;
    const float* src;
    float* dst;
    if (gw < NROW) { src = g_zflat + (size_t)gw * DIM; dst = g_S + gw; }
    else           { src = emb + (size_t)(gw - NROW) * DIM; dst = g_T + (gw - NROW); }
    const float4* s4 = (const float4*)src;
    float acc = 0.f;
    #pragma unroll 4
    for (int i = lane; i < DIM / 4; i += 32) {
        float4 v = s4[i];
        acc += v.x * v.x + v.y * v.y + v.z * v.z + v.w * v.w;
    }
    #pragma unroll
    for (int o = 16; o; o >>= 1) acc += __shfl_down_sync(0xffffffffu, acc, o);
    if (lane == 0) *dst = acc;
}

// ---------------- kernel 3: fused distance GEMM + per-tile argmin ------------
// 128x128 tile, BK=16, 256 threads, 8x8 microtile, double-buffered smem.
__global__ __launch_bounds__(256, 2)
void vq_dist_kernel(const float* __restrict__ emb) {
    const int tileN = blockIdx.x;   // code tile (64)
    const int tileM = blockIdx.y;   // row tile  (64)

    __shared__ float As[2][16][128];
    __shared__ float Bs[2][16][128];
    __shared__ float sv[128][16];
    __shared__ int   si[128][16];

    const int tid = threadIdx.x;
    const int tx = tid & 15;        // code sub (0..15)
    const int ty = tid >> 4;        // row sub  (0..15)

    const float* Aglob = g_zflat + (size_t)(tileM * 128) * DIM;
    const float* Bglob = emb     + (size_t)(tileN * 128) * DIM;

    float acc[8][8];
    #pragma unroll
    for (int i = 0; i < 8; i++)
        #pragma unroll
        for (int j = 0; j < 8; j++) acc[i][j] = 0.f;

    // stage-0 load (k0 = 0): 512 float4 per matrix; 2 per thread
    {
        #pragma unroll
        for (int p = 0; p < 2; p++) {
            int pos = tid + p * 256;
            int row = pos >> 2;
            int kq  = (pos & 3) << 2;
            float4 a = *(const float4*)(Aglob + (size_t)row * DIM + kq);
            As[0][kq + 0][row] = a.x; As[0][kq + 1][row] = a.y;
            As[0][kq + 2][row] = a.z; As[0][kq + 3][row] = a.w;
            float4 b = *(const float4*)(Bglob + (size_t)row * DIM + kq);
            Bs[0][kq + 0][row] = b.x; Bs[0][kq + 1][row] = b.y;
            Bs[0][kq + 2][row] = b.z; Bs[0][kq + 3][row] = b.w;
        }
    }
    __syncthreads();

    int s = 0;
    for (int kt = 0; kt < 64; kt++) {
        float4 ra[2], rb[2];
        const bool more = (kt < 63);
        if (more) {
            int k0 = (kt + 1) * 16;
            #pragma unroll
            for (int p = 0; p < 2; p++) {
                int pos = tid + p * 256;
                int row = pos >> 2;
                int kq  = (pos & 3) << 2;
                ra[p] = *(const float4*)(Aglob + (size_t)row * DIM + k0 + kq);
                rb[p] = *(const float4*)(Bglob + (size_t)row * DIM + k0 + kq);
            }
        }
        #pragma unroll
        for (int kk = 0; kk < 16; kk++) {
            float a[8], b[8];
            *(float4*)&a[0] = *(const float4*)&As[s][kk][ty * 8];
            *(float4*)&a[4] = *(const float4*)&As[s][kk][ty * 8 + 4];
            *(float4*)&b[0] = *(const float4*)&Bs[s][kk][tx * 8];
            *(float4*)&b[4] = *(const float4*)&Bs[s][kk][tx * 8 + 4];
            #pragma unroll
            for (int i = 0; i < 8; i++)
                #pragma unroll
                for (int j = 0; j < 8; j++)
                    acc[i][j] = fmaf(a[i], b[j], acc[i][j]);
        }
        if (more) {
            int d = s ^ 1;
            #pragma unroll
            for (int p = 0; p < 2; p++) {
                int pos = tid + p * 256;
                int row = pos >> 2;
                int kq  = (pos & 3) << 2;
                As[d][kq + 0][row] = ra[p].x; As[d][kq + 1][row] = ra[p].y;
                As[d][kq + 2][row] = ra[p].z; As[d][kq + 3][row] = ra[p].w;
                Bs[d][kq + 0][row] = rb[p].x; Bs[d][kq + 1][row] = rb[p].y;
                Bs[d][kq + 2][row] = rb[p].z; Bs[d][kq + 3][row] = rb[p].w;
            }
        }
        __syncthreads();
        s ^= 1;
    }

    // epilogue: d = fl(fl(S + T) - 2*P) exactly like the reference; argmin.
    const int row0 = tileM * 128 + ty * 8;
    const int col0 = tileN * 128 + tx * 8;
    #pragma unroll
    for (int i = 0; i < 8; i++) {
        float S = g_S[row0 + i];
        float bv = __int_as_float(0x7f800000);  // +inf
        int   bj = col0;
        #pragma unroll
        for (int j = 0; j < 8; j++) {
            float T = g_T[col0 + j];
            float Q = __fadd_rn(S, T);
            float d = __fsub_rn(Q, 2.0f * acc[i][j]);
            if (d < bv) { bv = d; bj = col0 + j; }   // strict < => lowest index on tie
        }
        sv[ty * 8 + i][tx] = bv;
        si[ty * 8 + i][tx] = bj;
    }
    __syncthreads();

    if (tid < 128) {
        float bv = sv[tid][0];
        int   bj = si[tid][0];
        #pragma unroll
        for (int x = 1; x < 16; x++) {
            float v = sv[tid][x];
            int   j = si[tid][x];
            // x ascending => idx ascending; strict < keeps the lowest index on ties
            if (v < bv) { bv = v; bj = j; }
        }
        int grow = tileM * 128 + tid;
        g_pval[(size_t)grow * 64 + tileN] = bv;
        g_pidx[(size_t)grow * 64 + tileN] = bj;
    }
}

// ---------------- kernel 4: reduce 64 tile-partials -> idx, hist, out idx ----
__global__ void vq_reduce_kernel(float* __restrict__ out) {
    int gw   = (blockIdx.x * blockDim.x + threadIdx.x) >> 5;
    int lane = threadIdx.x & 31;
    if (gw >= NROW) return;
    const float* pv = g_pval + (size_t)gw * 64;
    const int*   pi = g_pidx + (size_t)gw * 64;
    float v = pv[lane];        int ix = pi[lane];
    float v2 = pv[lane + 32];  int ix2 = pi[lane + 32];
    if (v2 < v || (v2 == v && ix2 < ix)) { v = v2; ix = ix2; }
    #pragma unroll
    for (int o = 16; o; o >>= 1) {
        float ov = __shfl_down_sync(0xffffffffu, v, o);
        int   oi = __shfl_down_sync(0xffffffffu, ix, o);
        if (ov < v || (ov == v && oi < ix)) { v = ov; ix = oi; }
    }
    if (lane == 0) {
        g_idx[gw] = ix;
        out[OFF_IDX + gw] = (float)ix;
        atomicAdd(&g_hist[ix], 1);
    }
}

// ---------------- kernel 5: gather codebook, STE output, loss accumulation ---
__global__ void vq_gather_kernel(const float* __restrict__ z,
                                 const float* __restrict__ emb,
                                 float* __restrict__ out) {
    int t = blockIdx.x * blockDim.x + threadIdx.x;   // indexes (b, c, hw) layout
    // t = ((b*1024 + c)*1024 + hw)
    int hw = t & 1023;
    int c  = (t >> 10) & 1023;
    int b  = t >> 20;
    int n  = (b << 10) | hw;
    int code = g_idx[n];
    float zv = z[t];
    float e  = emb[(size_t)code * DIM + c];
    float diff = __fsub_rn(e, zv);          // z_q - z (forward value)
    out[t] = __fadd_rn(zv, diff);           // straight-through: z + (zq - z), fp32-rounded
    float sq = diff * diff;

    // block reduce sq -> atomicAdd double
    #pragma unroll
    for (int o = 16; o; o >>= 1) sq += __shfl_down_sync(0xffffffffu, sq, o);
    __shared__ float warpsum[8];
    int lane = threadIdx.x & 31, wid = threadIdx.x >> 5;
    if (lane == 0) warpsum[wid] = sq;
    __syncthreads();
    if (wid == 0) {
        float v = (lane < 8) ? warpsum[lane] : 0.f;
        #pragma unroll
        for (int o = 4; o; o >>= 1) v += __shfl_down_sync(0xffffffffu, v, o);
        if (lane == 0) atomicAdd(&g_loss, (double)v);
    }
}

// ---------------- kernel 6: finalize loss + perplexity -----------------------
__global__ void vq_finalize_kernel(float* __restrict__ out) {
    __shared__ float warpsum[8];
    int tid = threadIdx.x;
    float s = 0.f;
    for (int k = tid; k < NCODE; k += 256) {
        float c = (float)g_hist[k];
        float p = c * (1.0f / (float)NROW);
        s += p * logf(p + 1e-10f);
    }
    #pragma unroll
    for (int o = 16; o; o >>= 1) s += __shfl_down_sync(0xffffffffu, s, o);
    int lane = tid & 31, wid = tid >> 5;
    if (lane == 0) warpsum[wid] = s;
    __syncthreads();
    if (wid == 0) {
        float v = (lane < 8) ? warpsum[lane] : 0.f;
        #pragma unroll
        for (int o = 4; o; o >>= 1) v += __shfl_down_sync(0xffffffffu, v, o);
        if (lane == 0) {
            out[OFF_PERP] = expf(-v);
            double m = g_loss / (double)ZQ_ELEMS;
            float mf = (float)m;
            out[OFF_LOSS] = __fadd_rn(mf, 0.25f * mf);   // legacy loss = m + beta*m
        }
    }
}

// ---------------- launch ------------------------------------------------------
extern "C" void kernel_launch(void* const* d_in, const int* in_sizes, int n_in,
                              void* d_out, int out_size) {
    const float* z   = (const float*)d_in[0];
    const float* emb = (const float*)d_in[1];
    float* out = (float*)d_out;
    (void)in_sizes; (void)n_in; (void)out_size;

    vq_zero_kernel<<<32, 256>>>();

    dim3 tb(32, 8);
    dim3 tg(32, 32, BATCH);
    vq_transpose_kernel<<<tg, tb>>>(z);

    vq_rowsum_kernel<<<(NROW + NCODE) * 32 / 256, 256>>>(emb);

    dim3 dg(NCODE / 128, NROW / 128);
    vq_dist_kernel<<<dg, 256>>>(emb);

    vq_reduce_kernel<<<NROW * 32 / 256, 256>>>(out);

    vq_gather_kernel<<<ZQ_ELEMS / 256, 256>>>(z, emb, out);

    vq_finalize_kernel<<<1, 256>>>(out);
}

// round 3
// speedup vs baseline: 4.4327x; 4.4327x over previous
#include <cuda_runtime.h>
#include <cuda_fp16.h>
#include <math.h>
#include <stdint.h>

// Problem constants
#define BATCH   8
#define DIM     1024
#define HW      1024
#define NROW    8192
#define NCODE   8192
#define ZQ_ELEMS (BATCH*DIM*HW)
#define OFF_LOSS  ZQ_ELEMS
#define OFF_PERP  (ZQ_ELEMS + 1)
#define OFF_IDX   (ZQ_ELEMS + 2)

#define ESCALE 512.0f       // codebook pre-scale (exact power of 2)
#define MARGIN 1e-3f

// ---------------- device scratch ---------------------------------------------
__device__ float   g_zflat[(size_t)NROW * DIM];    // 32 MB fp32 z rows
__device__ __half  g_zh[(size_t)NROW * DIM];       // 16 MB fp16 z rows
__device__ __half  g_eh[(size_t)NCODE * DIM];      // 16 MB fp16 codebook (x512)
__device__ float   g_S[NROW];
__device__ float   g_T[NCODE];
__device__ float   g_coarse[(size_t)NROW * NCODE]; // 256 MB coarse scores
__device__ int     g_idx[NROW];
__device__ int     g_hist[NCODE];
__device__ double  g_loss;

// ---------------- PTX helpers -------------------------------------------------
__device__ __forceinline__ uint32_t smem_u32(const void* p) {
    uint32_t a;
    asm("{ .reg .u64 t; cvta.to.shared.u64 t, %1; cvt.u32.u64 %0, t; }" : "=r"(a) : "l"(p));
    return a;
}
__device__ __forceinline__ void cp_async16(uint32_t saddr, const void* gptr) {
    asm volatile("cp.async.cg.shared.global [%0], [%1], 16;" :: "r"(saddr), "l"(gptr));
}
__device__ __forceinline__ void cp_commit() { asm volatile("cp.async.commit_group;" ::: "memory"); }
__device__ __forceinline__ void cp_wait0()  { asm volatile("cp.async.wait_group 0;" ::: "memory"); }

__device__ __forceinline__ void ldsm_x4(uint32_t* r, uint32_t addr) {
    asm volatile("ldmatrix.sync.aligned.m8n8.x4.shared.b16 {%0,%1,%2,%3}, [%4];"
                 : "=r"(r[0]), "=r"(r[1]), "=r"(r[2]), "=r"(r[3]) : "r"(addr));
}
__device__ __forceinline__ void mma16816(float* d, const uint32_t* a, uint32_t b0, uint32_t b1) {
    asm volatile("mma.sync.aligned.m16n8k16.row.col.f32.f16.f16.f32 "
                 "{%0,%1,%2,%3}, {%4,%5,%6,%7}, {%8,%9}, {%0,%1,%2,%3};"
                 : "+f"(d[0]), "+f"(d[1]), "+f"(d[2]), "+f"(d[3])
                 : "r"(a[0]), "r"(a[1]), "r"(a[2]), "r"(a[3]), "r"(b0), "r"(b1));
}

// ---------------- kernel 0: zero accumulators --------------------------------
__global__ void vq_zero_kernel() {
    int t = blockIdx.x * blockDim.x + threadIdx.x;
    if (t < NCODE) g_hist[t] = 0;
    if (t == 0) g_loss = 0.0;
}

// ---------------- kernel 1: transpose z -> zflat (fp32 + fp16) ---------------
__global__ void vq_transpose_kernel(const float* __restrict__ z) {
    __shared__ float tile[32][33];
    int b = blockIdx.z;
    int hw0 = blockIdx.x * 32;
    int c0  = blockIdx.y * 32;
    const float* src = z + ((size_t)b << 20);
    float* dst = g_zflat + ((size_t)b << 20);
    __half* dsth = g_zh + ((size_t)b << 20);
    #pragma unroll
    for (int r = threadIdx.y; r < 32; r += 8)
        tile[r][threadIdx.x] = src[(size_t)(c0 + r) * HW + hw0 + threadIdx.x];
    __syncthreads();
    #pragma unroll
    for (int r = threadIdx.y; r < 32; r += 8) {
        float v = tile[threadIdx.x][r];
        size_t o = (size_t)(hw0 + r) * DIM + c0 + threadIdx.x;
        dst[o]  = v;
        dsth[o] = __float2half_rn(v);
    }
}

// ---------------- kernel 2: row norms + emb fp16 (scaled) conversion ---------
__global__ void vq_rowsum_kernel(const float* __restrict__ emb) {
    int gw   = (blockIdx.x * blockDim.x + threadIdx.x) >> 5;
    int lane = threadIdx.x & 31;
    if (gw >= NROW + NCODE) return;
    const float* src;
    float* dst;
    bool isEmb = (gw >= NROW);
    if (!isEmb) { src = g_zflat + (size_t)gw * DIM; dst = g_S + gw; }
    else        { src = emb + (size_t)(gw - NROW) * DIM; dst = g_T + (gw - NROW); }
    const float4* s4 = (const float4*)src;
    __half2* eh2 = isEmb ? (__half2*)(g_eh + (size_t)(gw - NROW) * DIM) : nullptr;
    float acc = 0.f;
    #pragma unroll 4
    for (int i = lane; i < DIM / 4; i += 32) {
        float4 v = s4[i];
        if (isEmb) {
            eh2[i * 2]     = __floats2half2_rn(v.x * ESCALE, v.y * ESCALE);
            eh2[i * 2 + 1] = __floats2half2_rn(v.z * ESCALE, v.w * ESCALE);
        }
        acc += v.x * v.x + v.y * v.y + v.z * v.z + v.w * v.w;
    }
    #pragma unroll
    for (int o = 16; o; o >>= 1) acc += __shfl_down_sync(0xffffffffu, acc, o);
    if (lane == 0) *dst = acc;
}

// ---------------- kernel 3: fp16 HMMA GEMM -> coarse scores ------------------
// CTA 128 (z rows, M) x 128 (codes, N), BK=32, 8 warps (2x4), warp 64x32.
#define AS_OFF(s) ((s) * 10240u)
#define BS_OFF(s) (20480u + (s) * 10240u)

__global__ __launch_bounds__(256, 2)
void vq_mm_kernel() {
    __shared__ __align__(128) uint8_t smem[40960];
    const uint32_t sb = smem_u32(smem);
    const int tid = threadIdx.x;
    const int lane = tid & 31, wid = tid >> 5;
    const int warpM = wid >> 2, warpN = wid & 3;
    const int rowBase  = blockIdx.y * 128;
    const int codeBase = blockIdx.x * 128;

    // cp.async task: row = tid>>1, chunks (tid&1)*2 + {0,1}
    const int ldrow = tid >> 1;
    const int ldc0  = (tid & 1) * 2;
    const __half* gA = g_zh + (size_t)(rowBase + ldrow) * DIM + ldc0 * 8;
    const __half* gB = g_eh + (size_t)(codeBase + ldrow) * DIM + ldc0 * 8;
    const uint32_t stA = (uint32_t)ldrow * 80u + (uint32_t)ldc0 * 16u;

    // ldmatrix lane addressing
    const uint32_t a_base = (uint32_t)((warpM * 64 + (lane & 15)) * 80 + ((lane >> 4) * 8) * 2);
    const int grp = lane >> 3;
    const uint32_t b_base = (uint32_t)((warpN * 32 + ((grp >> 1) * 8) + (lane & 7)) * 80
                                       + ((grp & 1) * 8) * 2);

    float acc[4][4][4];
    #pragma unroll
    for (int i = 0; i < 4; i++)
        #pragma unroll
        for (int j = 0; j < 4; j++)
            #pragma unroll
            for (int k = 0; k < 4; k++) acc[i][j][k] = 0.f;

    // prefetch stage 0
    {
        uint32_t a0 = sb + AS_OFF(0) + stA;
        cp_async16(a0,      gA);
        cp_async16(a0 + 16, gA + 8);
        uint32_t b0 = sb + BS_OFF(0) + stA;
        cp_async16(b0,      gB);
        cp_async16(b0 + 16, gB + 8);
        cp_commit();
    }

    #pragma unroll 1
    for (int kt = 0; kt < 32; kt++) {
        cp_wait0();
        __syncthreads();
        if (kt < 31) {
            int k0 = (kt + 1) * 32;
            int s  = (kt + 1) & 1;
            uint32_t a0 = sb + AS_OFF(s) + stA;
            cp_async16(a0,      gA + k0);
            cp_async16(a0 + 16, gA + k0 + 8);
            uint32_t b0 = sb + BS_OFF(s) + stA;
            cp_async16(b0,      gB + k0);
            cp_async16(b0 + 16, gB + k0 + 8);
            cp_commit();
        }
        const int s = kt & 1;
        const uint32_t As0 = sb + AS_OFF(s) + a_base;
        const uint32_t Bs0 = sb + BS_OFF(s) + b_base;
        #pragma unroll
        for (int ks = 0; ks < 2; ks++) {
            uint32_t a[4][4], b[2][4];
            #pragma unroll
            for (int mt = 0; mt < 4; mt++) ldsm_x4(a[mt], As0 + mt * 16 * 80 + ks * 32);
            #pragma unroll
            for (int pr = 0; pr < 2; pr++)  ldsm_x4(b[pr], Bs0 + pr * 16 * 80 + ks * 32);
            #pragma unroll
            for (int mt = 0; mt < 4; mt++)
                #pragma unroll
                for (int nt = 0; nt < 4; nt++)
                    mma16816(acc[mt][nt], a[mt], b[nt >> 1][(nt & 1) * 2], b[nt >> 1][(nt & 1) * 2 + 1]);
        }
    }

    // epilogue: coarse = fl(S+T) - (2/ESCALE)*P
    const float inv2 = 2.0f / ESCALE;
    #pragma unroll
    for (int mt = 0; mt < 4; mt++) {
        int r0 = rowBase + warpM * 64 + mt * 16 + (lane >> 2);
        float S0 = g_S[r0], S1 = g_S[r0 + 8];
        #pragma unroll
        for (int nt = 0; nt < 4; nt++) {
            int c0 = codeBase + warpN * 32 + nt * 8 + (lane & 3) * 2;
            float T0 = g_T[c0], T1 = g_T[c0 + 1];
            float2 v0, v1;
            v0.x = __fsub_rn(__fadd_rn(S0, T0), inv2 * acc[mt][nt][0]);
            v0.y = __fsub_rn(__fadd_rn(S0, T1), inv2 * acc[mt][nt][1]);
            v1.x = __fsub_rn(__fadd_rn(S1, T0), inv2 * acc[mt][nt][2]);
            v1.y = __fsub_rn(__fadd_rn(S1, T1), inv2 * acc[mt][nt][3]);
            *(float2*)(g_coarse + (size_t)r0 * NCODE + c0)       = v0;
            *(float2*)(g_coarse + (size_t)(r0 + 8) * NCODE + c0) = v1;
        }
    }
}

// ---------------- kernel 4: scan coarse row -> candidates -> exact rescore ---
__global__ __launch_bounds__(256, 4)
void vq_scan_kernel(const float* __restrict__ emb, float* __restrict__ out) {
    const int n = blockIdx.x;
    const int t = threadIdx.x;
    const int lane = t & 31, w = t >> 5;

    __shared__ float s_ws[8];
    __shared__ float s_min;
    __shared__ int   s_cnt;
    __shared__ int   s_cand[96];
    __shared__ float s_bd;
    __shared__ int   s_bk;

    const float4* crow = (const float4*)(g_coarse + (size_t)n * NCODE);
    float4 v[8];
    float lm = __int_as_float(0x7f800000);
    #pragma unroll
    for (int i = 0; i < 8; i++) {
        v[i] = crow[t + 256 * i];
        lm = fminf(lm, fminf(fminf(v[i].x, v[i].y), fminf(v[i].z, v[i].w)));
    }
    #pragma unroll
    for (int o = 16; o; o >>= 1) lm = fminf(lm, __shfl_down_sync(0xffffffffu, lm, o));
    if (lane == 0) s_ws[w] = lm;
    if (t == 0) s_cnt = 0;
    __syncthreads();
    if (t == 0) {
        float m = s_ws[0];
        #pragma unroll
        for (int i = 1; i < 8; i++) m = fminf(m, s_ws[i]);
        s_min = m;
    }
    __syncthreads();
    const float thresh = s_min + MARGIN;
    #pragma unroll
    for (int i = 0; i < 8; i++) {
        int kbase = (t + 256 * i) * 4;
        if (v[i].x <= thresh) { int p = atomicAdd(&s_cnt, 1); if (p < 96) s_cand[p] = kbase; }
        if (v[i].y <= thresh) { int p = atomicAdd(&s_cnt, 1); if (p < 96) s_cand[p] = kbase + 1; }
        if (v[i].z <= thresh) { int p = atomicAdd(&s_cnt, 1); if (p < 96) s_cand[p] = kbase + 2; }
        if (v[i].w <= thresh) { int p = atomicAdd(&s_cnt, 1); if (p < 96) s_cand[p] = kbase + 3; }
    }
    __syncthreads();
    int cnt = s_cnt < 96 ? s_cnt : 96;

    const float4 zv = ((const float4*)(g_zflat + (size_t)n * DIM))[t];
    const float S = g_S[n];
    if (t == 0) { s_bd = __int_as_float(0x7f800000); s_bk = 0x7fffffff; }
    __syncthreads();

    for (int c = 0; c < cnt; c++) {
        int k = s_cand[c];
        float4 ev = ((const float4*)(emb + (size_t)k * DIM))[t];
        float p = fmaf(zv.x, ev.x, fmaf(zv.y, ev.y, fmaf(zv.z, ev.z, zv.w * ev.w)));
        #pragma unroll
        for (int o = 16; o; o >>= 1) p += __shfl_down_sync(0xffffffffu, p, o);
        if (lane == 0) s_ws[w] = p;
        __syncthreads();
        if (t == 0) {
            float P = 0.f;
            #pragma unroll
            for (int i = 0; i < 8; i++) P += s_ws[i];
            float T = g_T[k];
            float d = __fsub_rn(__fadd_rn(S, T), 2.0f * P);
            if (d < s_bd || (d == s_bd && k < s_bk)) { s_bd = d; s_bk = k; }
        }
        __syncthreads();
    }
    if (t == 0) {
        int bk = s_bk;
        g_idx[n] = bk;
        out[OFF_IDX + n] = (float)bk;
        atomicAdd(&g_hist[bk], 1);
    }
}

// ---------------- kernel 5: gather codebook, STE output, loss ----------------
__global__ void vq_gather_kernel(const float* __restrict__ z,
                                 const float* __restrict__ emb,
                                 float* __restrict__ out) {
    int t = blockIdx.x * blockDim.x + threadIdx.x;
    int hw = t & 1023;
    int c  = (t >> 10) & 1023;
    int b  = t >> 20;
    int n  = (b << 10) | hw;
    int code = g_idx[n];
    float zv = z[t];
    float e  = emb[(size_t)code * DIM + c];
    float diff = __fsub_rn(e, zv);
    out[t] = __fadd_rn(zv, diff);
    float sq = diff * diff;
    #pragma unroll
    for (int o = 16; o; o >>= 1) sq += __shfl_down_sync(0xffffffffu, sq, o);
    __shared__ float warpsum[8];
    int lane = threadIdx.x & 31, wid = threadIdx.x >> 5;
    if (lane == 0) warpsum[wid] = sq;
    __syncthreads();
    if (wid == 0) {
        float v = (lane < 8) ? warpsum[lane] : 0.f;
        #pragma unroll
        for (int o = 4; o; o >>= 1) v += __shfl_down_sync(0xffffffffu, v, o);
        if (lane == 0) atomicAdd(&g_loss, (double)v);
    }
}

// ---------------- kernel 6: finalize loss + perplexity -----------------------
__global__ void vq_finalize_kernel(float* __restrict__ out) {
    __shared__ float warpsum[8];
    int tid = threadIdx.x;
    float s = 0.f;
    for (int k = tid; k < NCODE; k += 256) {
        float c = (float)g_hist[k];
        float p = c * (1.0f / (float)NROW);
        s += p * logf(p + 1e-10f);
    }
    #pragma unroll
    for (int o = 16; o; o >>= 1) s += __shfl_down_sync(0xffffffffu, s, o);
    int lane = tid & 31, wid = tid >> 5;
    if (lane == 0) warpsum[wid] = s;
    __syncthreads();
    if (wid == 0) {
        float v = (lane < 8) ? warpsum[lane] : 0.f;
        #pragma unroll
        for (int o = 4; o; o >>= 1) v += __shfl_down_sync(0xffffffffu, v, o);
        if (lane == 0) {
            out[OFF_PERP] = expf(-v);
            double m = g_loss / (double)ZQ_ELEMS;
            float mf = (float)m;
            out[OFF_LOSS] = __fadd_rn(mf, 0.25f * mf);
        }
    }
}

// ---------------- launch ------------------------------------------------------
extern "C" void kernel_launch(void* const* d_in, const int* in_sizes, int n_in,
                              void* d_out, int out_size) {
    const float* z   = (const float*)d_in[0];
    const float* emb = (const float*)d_in[1];
    float* out = (float*)d_out;
    (void)in_sizes; (void)n_in; (void)out_size;

    vq_zero_kernel<<<32, 256>>>();

    dim3 tb(32, 8);
    dim3 tg(32, 32, BATCH);
    vq_transpose_kernel<<<tg, tb>>>(z);

    vq_rowsum_kernel<<<(NROW + NCODE) * 32 / 256, 256>>>(emb);

    dim3 mg(NCODE / 128, NROW / 128);
    vq_mm_kernel<<<mg, 256>>>();

    vq_scan_kernel<<<NROW, 256>>>(emb, out);

    vq_gather_kernel<<<ZQ_ELEMS / 256, 256>>>(z, emb, out);

    vq_finalize_kernel<<<1, 256>>>(out);
}